// round 1
// baseline (speedup 1.0000x reference)
#include <cuda_runtime.h>
#include <math.h>

#define KDIM     4096
#define NJ       24          // 4 pre + 4 post + 16 res
#define ROWS     64          // rows per block
#define BLOCK    256
#define KC       128         // K-chunk staged in smem
#define RMS_EPS  1.1920928955078125e-07f
#define SK_EPS   1e-6f

// Pre-scaled, k-major weight matrix: W'[k][j] = alpha_g(j) * norm_w[k] * W_j[k]
__device__ float g_Wt[KDIM * NJ];

__global__ void prep_kernel(const float* __restrict__ norm_w,
                            const float* __restrict__ W_pre,
                            const float* __restrict__ W_post,
                            const float* __restrict__ W_res,
                            const float* __restrict__ a_pre,
                            const float* __restrict__ a_post,
                            const float* __restrict__ a_res) {
    int idx = blockIdx.x * blockDim.x + threadIdx.x;
    if (idx >= KDIM * NJ) return;
    int k = idx / NJ;
    int j = idx - k * NJ;
    float w, a;
    if (j < 4)      { w = W_pre [j * KDIM + k];       a = a_pre[0];  }
    else if (j < 8) { w = W_post[(j - 4) * KDIM + k]; a = a_post[0]; }
    else            { w = W_res [(j - 8) * KDIM + k]; a = a_res[0];  }
    g_Wt[k * NJ + j] = w * a * norm_w[k];
}

__global__ __launch_bounds__(BLOCK, 2)
void mhc_main_kernel(const float* __restrict__ x,
                     const float* __restrict__ b_pre,
                     const float* __restrict__ b_post,
                     const float* __restrict__ b_res,
                     float* __restrict__ out, int Btot) {
    // x tile transposed: xs[k_local][row], stride 65 (odd) -> conflict-free STS & LDS
    __shared__ float xs[KC * 65];
    __shared__ float sAcc[ROWS * 25];   // 24 dots + ssq per row

    const int tid  = threadIdx.x;
    const int lane = tid & 31;
    const int warp = tid >> 5;
    const int rowbase = blockIdx.x * ROWS;

    for (int i = tid; i < ROWS * 25; i += BLOCK) sAcc[i] = 0.0f;

    float accA[NJ], accB[NJ];
    float ssqA = 0.0f, ssqB = 0.0f;
#pragma unroll
    for (int j = 0; j < NJ; j++) { accA[j] = 0.0f; accB[j] = 0.0f; }

    for (int kc = 0; kc < KDIM; kc += KC) {
        __syncthreads();   // xs safe to overwrite (also orders sAcc init on 1st pass)
        // Cooperative coalesced load + transpose into smem.
#pragma unroll
        for (int i = 0; i < (ROWS * KC) / BLOCK; i++) {
            int idx = i * BLOCK + tid;
            int row = idx >> 7;          // idx / KC
            int kl  = idx & (KC - 1);
            xs[kl * 65 + row] = x[(size_t)(rowbase + row) * KDIM + kc + kl];
        }
        __syncthreads();

        // Each warp handles a disjoint 16-wide k-slice of this chunk.
        const int k0 = warp * (KC / 8);
#pragma unroll 2
        for (int t = 0; t < KC / 8; t++) {
            const int kl = k0 + t;
            const int k  = kc + kl;
            const float4* wr = reinterpret_cast<const float4*>(&g_Wt[k * NJ]);
            // warp-uniform weight loads (k identical across lanes)
            float4 w0 = wr[0], w1 = wr[1], w2 = wr[2];
            float4 w3 = wr[3], w4 = wr[4], w5 = wr[5];
            float xa = xs[kl * 65 + lane];
            float xb = xs[kl * 65 + lane + 32];
            ssqA += xa * xa;
            ssqB += xb * xb;
            const float w[NJ] = { w0.x,w0.y,w0.z,w0.w, w1.x,w1.y,w1.z,w1.w,
                                  w2.x,w2.y,w2.z,w2.w, w3.x,w3.y,w3.z,w3.w,
                                  w4.x,w4.y,w4.z,w4.w, w5.x,w5.y,w5.z,w5.w };
#pragma unroll
            for (int j = 0; j < NJ; j++) {
                accA[j] += xa * w[j];
                accB[j] += xb * w[j];
            }
        }
    }

    // Cross-warp reduction (each (row,j) hit by 8 warps -> light contention).
#pragma unroll
    for (int j = 0; j < NJ; j++) {
        atomicAdd(&sAcc[lane * 25 + j],        accA[j]);
        atomicAdd(&sAcc[(lane + 32) * 25 + j], accB[j]);
    }
    atomicAdd(&sAcc[lane * 25 + 24],        ssqA);
    atomicAdd(&sAcc[(lane + 32) * 25 + 24], ssqB);
    __syncthreads();

    // Epilogue: one thread per row.
    if (tid < ROWS) {
        const int row = rowbase + tid;
        const float* a = &sAcc[tid * 25];
        const float rinv = rsqrtf(a[24] * (1.0f / (float)KDIM) + RMS_EPS);

#pragma unroll
        for (int j = 0; j < 4; j++) {
            float p = rinv * a[j] + b_pre[j];
            out[(size_t)row * 4 + j] = __fdividef(1.0f, 1.0f + __expf(-p));
        }
#pragma unroll
        for (int j = 0; j < 4; j++) {
            float p = rinv * a[4 + j] + b_post[j];
            out[(size_t)Btot * 4 + (size_t)row * 4 + j] =
                2.0f * __fdividef(1.0f, 1.0f + __expf(-p));
        }

        float M[16];
#pragma unroll
        for (int j = 0; j < 16; j++)
            M[j] = __expf(rinv * a[8 + j] + b_res[j]);

#pragma unroll 1
        for (int it = 0; it < 20; it++) {
#pragma unroll
            for (int r = 0; r < 4; r++) {
                float s = M[4*r] + M[4*r+1] + M[4*r+2] + M[4*r+3] + SK_EPS;
                float inv = __fdividef(1.0f, s);
                M[4*r] *= inv; M[4*r+1] *= inv; M[4*r+2] *= inv; M[4*r+3] *= inv;
            }
#pragma unroll
            for (int c = 0; c < 4; c++) {
                float s = M[c] + M[c+4] + M[c+8] + M[c+12] + SK_EPS;
                float inv = __fdividef(1.0f, s);
                M[c] *= inv; M[c+4] *= inv; M[c+8] *= inv; M[c+12] *= inv;
            }
        }
#pragma unroll
        for (int j = 0; j < 16; j++)
            out[(size_t)Btot * 8 + (size_t)row * 16 + j] = M[j];
    }
}

extern "C" void kernel_launch(void* const* d_in, const int* in_sizes, int n_in,
                              void* d_out, int out_size) {
    const float* x      = (const float*)d_in[0];
    const float* norm_w = (const float*)d_in[1];
    const float* W_pre  = (const float*)d_in[2];
    const float* W_post = (const float*)d_in[3];
    const float* W_res  = (const float*)d_in[4];
    const float* b_pre  = (const float*)d_in[5];
    const float* b_post = (const float*)d_in[6];
    const float* b_res  = (const float*)d_in[7];
    const float* a_pre  = (const float*)d_in[8];
    const float* a_post = (const float*)d_in[9];
    const float* a_res  = (const float*)d_in[10];

    const int Btot = in_sizes[0] / KDIM;

    prep_kernel<<<(KDIM * NJ + 255) / 256, 256>>>(norm_w, W_pre, W_post, W_res,
                                                  a_pre, a_post, a_res);
    mhc_main_kernel<<<Btot / ROWS, BLOCK>>>(x, b_pre, b_post, b_res,
                                            (float*)d_out, Btot);
}

// round 2
// speedup vs baseline: 2.3251x; 2.3251x over previous
#include <cuda_runtime.h>
#include <math.h>
#include <stdint.h>

#define KDIM     4096
#define NJ       24          // 4 pre + 4 post + 16 res
#define ROWS     64          // rows per block
#define BLOCK    256
#define KC       128         // K-chunk staged in smem
#define NCHUNK   (KDIM / KC)
#define RMS_EPS  1.1920928955078125e-07f
#define SK_EPS   1e-6f

// Pre-scaled, k-major weight matrix: W'[k][j] = alpha_g(j) * norm_w[k] * W_j[k]
__device__ __align__(16) float g_Wt[KDIM * NJ];

// ---------- packed f32x2 helpers ----------
__device__ __forceinline__ unsigned long long pack2(float lo, float hi) {
    unsigned long long r;
    asm("mov.b64 %0, {%1, %2};" : "=l"(r) : "f"(lo), "f"(hi));
    return r;
}
__device__ __forceinline__ void unpack2(unsigned long long v, float& lo, float& hi) {
    asm("mov.b64 {%0, %1}, %2;" : "=f"(lo), "=f"(hi) : "l"(v));
}
__device__ __forceinline__ unsigned long long ffma2(unsigned long long a,
                                                    unsigned long long b,
                                                    unsigned long long c) {
    unsigned long long d;
    asm("fma.rn.f32x2 %0, %1, %2, %3;" : "=l"(d) : "l"(a), "l"(b), "l"(c));
    return d;
}

// ---------- cp.async helpers ----------
__device__ __forceinline__ void cp16cg(uint32_t dst, const void* src) {
    asm volatile("cp.async.cg.shared.global [%0], [%1], 16;" :: "r"(dst), "l"(src));
}
__device__ __forceinline__ void cp16ca(uint32_t dst, const void* src) {
    asm volatile("cp.async.ca.shared.global [%0], [%1], 16;" :: "r"(dst), "l"(src));
}
__device__ __forceinline__ void cp_commit() {
    asm volatile("cp.async.commit_group;");
}
template <int N>
__device__ __forceinline__ void cp_wait() {
    asm volatile("cp.async.wait_group %0;" :: "n"(N));
}
__device__ __forceinline__ uint32_t smem_u32(const void* p) {
    return (uint32_t)__cvta_generic_to_shared(p);
}

__global__ void prep_kernel(const float* __restrict__ norm_w,
                            const float* __restrict__ W_pre,
                            const float* __restrict__ W_post,
                            const float* __restrict__ W_res,
                            const float* __restrict__ a_pre,
                            const float* __restrict__ a_post,
                            const float* __restrict__ a_res) {
    int idx = blockIdx.x * blockDim.x + threadIdx.x;
    if (idx >= KDIM * NJ) return;
    int k = idx / NJ;
    int j = idx - k * NJ;
    float w, a;
    if (j < 4)      { w = W_pre [j * KDIM + k];       a = a_pre[0];  }
    else if (j < 8) { w = W_post[(j - 4) * KDIM + k]; a = a_post[0]; }
    else            { w = W_res [(j - 8) * KDIM + k]; a = a_res[0];  }
    g_Wt[k * NJ + j] = w * a * norm_w[k];
}

// Dynamic smem layout (bytes):
//   xs4 : 2 * 2048 float4  (x tiles, XOR-swizzled)        = 65536
//   ws  : 2 * 3072 float   (weight tiles, k-major)        = 24576
//   sAcc: 64 * 25 float                                   =  6400
#define XS4_COUNT  2048
#define WS_COUNT   3072
#define SMEM_BYTES (2 * XS4_COUNT * 16 + 2 * WS_COUNT * 4 + ROWS * 25 * 4)

__global__ __launch_bounds__(BLOCK, 2)
void mhc_main_kernel(const float* __restrict__ x,
                     const float* __restrict__ b_pre,
                     const float* __restrict__ b_post,
                     const float* __restrict__ b_res,
                     float* __restrict__ out, int Btot) {
    extern __shared__ float smem[];
    float4* xs4  = reinterpret_cast<float4*>(smem);          // [2][64][32]
    float*  ws   = smem + 2 * XS4_COUNT * 4;                 // [2][128*24]
    float*  sAcc = ws + 2 * WS_COUNT;                        // [64][25]

    const int tid  = threadIdx.x;
    const int lane = tid & 31;
    const int warp = tid >> 5;
    const int rowbase = blockIdx.x * ROWS;

    for (int i = tid; i < ROWS * 25; i += BLOCK) sAcc[i] = 0.0f;

    unsigned long long accA[12], accB[12], ssq = 0ull;
#pragma unroll
    for (int j = 0; j < 12; j++) { accA[j] = 0ull; accB[j] = 0ull; }

    // --- async chunk loader ---
    const float* xrowbase = x + (size_t)rowbase * KDIM;
    auto issue_chunk = [&](int c, int p) {
        const float* xb = xrowbase + c * KC;
#pragma unroll
        for (int i = 0; i < 8; i++) {               // 2048 float4, 8 per thread
            int idx = i * BLOCK + tid;
            int row = idx >> 5;
            int klv = idx & 31;
            uint32_t dst = smem_u32(&xs4[p * XS4_COUNT + row * 32 + (klv ^ (row & 31))]);
            cp16cg(dst, xb + (size_t)row * KDIM + klv * 4);
        }
        const float* wb = g_Wt + c * KC * NJ;
#pragma unroll
        for (int i = 0; i < 3; i++) {               // 768 float4, 3 per thread
            int idx = i * BLOCK + tid;
            uint32_t dst = smem_u32(&ws[p * WS_COUNT + idx * 4]);
            cp16ca(dst, wb + idx * 4);
        }
        cp_commit();
    };

    issue_chunk(0, 0);

    for (int c = 0; c < NCHUNK; c++) {
        const int p = c & 1;
        if (c + 1 < NCHUNK) {
            issue_chunk(c + 1, 1 - p);
            cp_wait<1>();
        } else {
            cp_wait<0>();
        }
        __syncthreads();

        // each warp covers 16 k of this 128-chunk (4 float4 groups)
#pragma unroll
        for (int t = 0; t < 4; t++) {
            const int klv = (warp << 2) + t;
            float4 xAv = xs4[p * XS4_COUNT + lane * 32 + (klv ^ lane)];
            float4 xBv = xs4[p * XS4_COUNT + (lane + 32) * 32 + (klv ^ lane)];
            const float xa_[4] = { xAv.x, xAv.y, xAv.z, xAv.w };
            const float xb_[4] = { xBv.x, xBv.y, xBv.z, xBv.w };
#pragma unroll
            for (int cc = 0; cc < 4; cc++) {
                const int kl = klv * 4 + cc;
                const ulonglong2* wp =
                    reinterpret_cast<const ulonglong2*>(&ws[p * WS_COUNT + kl * NJ]);
                ulonglong2 u0 = wp[0], u1 = wp[1], u2 = wp[2];
                ulonglong2 u3 = wp[3], u4 = wp[4], u5 = wp[5];
                const float xa = xa_[cc], xb = xb_[cc];
                unsigned long long xaa = pack2(xa, xa);
                unsigned long long xbb = pack2(xb, xb);
                unsigned long long xab = pack2(xa, xb);
                ssq = ffma2(xab, xab, ssq);
                const unsigned long long wv[12] = { u0.x, u0.y, u1.x, u1.y,
                                                    u2.x, u2.y, u3.x, u3.y,
                                                    u4.x, u4.y, u5.x, u5.y };
#pragma unroll
                for (int jp = 0; jp < 12; jp++) {
                    accA[jp] = ffma2(xaa, wv[jp], accA[jp]);
                    accB[jp] = ffma2(xbb, wv[jp], accB[jp]);
                }
            }
        }
        __syncthreads();   // buffer p may be overwritten next iteration
    }

    // cross-warp reduction (8 warps hit each (row,j))
#pragma unroll
    for (int jp = 0; jp < 12; jp++) {
        float a0, a1, b0, b1;
        unpack2(accA[jp], a0, a1);
        unpack2(accB[jp], b0, b1);
        atomicAdd(&sAcc[lane * 25 + 2 * jp],            a0);
        atomicAdd(&sAcc[lane * 25 + 2 * jp + 1],        a1);
        atomicAdd(&sAcc[(lane + 32) * 25 + 2 * jp],     b0);
        atomicAdd(&sAcc[(lane + 32) * 25 + 2 * jp + 1], b1);
    }
    {
        float sa, sb;
        unpack2(ssq, sa, sb);
        atomicAdd(&sAcc[lane * 25 + 24],        sa);
        atomicAdd(&sAcc[(lane + 32) * 25 + 24], sb);
    }
    __syncthreads();

    // epilogue: one thread per row
    if (tid < ROWS) {
        const int row = rowbase + tid;
        const float* a = &sAcc[tid * 25];
        const float rinv = rsqrtf(a[24] * (1.0f / (float)KDIM) + RMS_EPS);

#pragma unroll
        for (int j = 0; j < 4; j++) {
            float p = rinv * a[j] + b_pre[j];
            out[(size_t)row * 4 + j] = __fdividef(1.0f, 1.0f + __expf(-p));
        }
#pragma unroll
        for (int j = 0; j < 4; j++) {
            float p = rinv * a[4 + j] + b_post[j];
            out[(size_t)Btot * 4 + (size_t)row * 4 + j] =
                2.0f * __fdividef(1.0f, 1.0f + __expf(-p));
        }

        float M[16];
#pragma unroll
        for (int j = 0; j < 16; j++)
            M[j] = __expf(rinv * a[8 + j] + b_res[j]);

#pragma unroll 1
        for (int it = 0; it < 20; it++) {
#pragma unroll
            for (int r = 0; r < 4; r++) {
                float s = M[4*r] + M[4*r+1] + M[4*r+2] + M[4*r+3] + SK_EPS;
                float inv = __fdividef(1.0f, s);
                M[4*r] *= inv; M[4*r+1] *= inv; M[4*r+2] *= inv; M[4*r+3] *= inv;
            }
#pragma unroll
            for (int cq = 0; cq < 4; cq++) {
                float s = M[cq] + M[cq+4] + M[cq+8] + M[cq+12] + SK_EPS;
                float inv = __fdividef(1.0f, s);
                M[cq] *= inv; M[cq+4] *= inv; M[cq+8] *= inv; M[cq+12] *= inv;
            }
        }
#pragma unroll
        for (int j = 0; j < 16; j++)
            out[(size_t)Btot * 8 + (size_t)row * 16 + j] = M[j];
    }
}

extern "C" void kernel_launch(void* const* d_in, const int* in_sizes, int n_in,
                              void* d_out, int out_size) {
    const float* x      = (const float*)d_in[0];
    const float* norm_w = (const float*)d_in[1];
    const float* W_pre  = (const float*)d_in[2];
    const float* W_post = (const float*)d_in[3];
    const float* W_res  = (const float*)d_in[4];
    const float* b_pre  = (const float*)d_in[5];
    const float* b_post = (const float*)d_in[6];
    const float* b_res  = (const float*)d_in[7];
    const float* a_pre  = (const float*)d_in[8];
    const float* a_post = (const float*)d_in[9];
    const float* a_res  = (const float*)d_in[10];

    const int Btot = in_sizes[0] / KDIM;

    static bool attr_done = false;
    if (!attr_done) {
        cudaFuncSetAttribute(mhc_main_kernel,
                             cudaFuncAttributeMaxDynamicSharedMemorySize,
                             SMEM_BYTES);
        attr_done = true;
    }

    prep_kernel<<<(KDIM * NJ + 255) / 256, 256>>>(norm_w, W_pre, W_post, W_res,
                                                  a_pre, a_post, a_res);
    mhc_main_kernel<<<Btot / ROWS, BLOCK, SMEM_BYTES>>>(x, b_pre, b_post, b_res,
                                                        (float*)d_out, Btot);
}

// round 6
// speedup vs baseline: 3.6057x; 1.5508x over previous
#include <cuda_runtime.h>
#include <math.h>
#include <stdint.h>

#define KDIM     4096
#define NJ       24             // 4 pre + 4 post + 16 res
#define MM       256            // rows per CTA
#define BLOCK    256
#define KC       32             // k per chunk
#define NC       (KDIM / KC)    // 128 chunks
#define XSTR     36             // floats per staged row (36 % 32 == 4 -> conflict-free frags)
#define STAGEF   ((MM + NJ) * XSTR)        // floats per stage = 10080
#define WOFF     (MM * XSTR)               // weights offset inside stage (floats)
#define NSTG     5
#define SMEM_BYTES (NSTG * STAGEF * 4)     // 201600 B
#define SDSTR    28             // epilogue transpose stride
#define RMS_EPS  1.1920928955078125e-07f
#define SK_EPS   1e-6f

__device__ __align__(16) float g_Wt[NJ * KDIM];   // j-major, k contiguous, pre-scaled

// ---------------- helpers ----------------
__device__ __forceinline__ uint32_t smem_u32(const void* p) {
    return (uint32_t)__cvta_generic_to_shared(p);
}
__device__ __forceinline__ void cp16cg(uint32_t dst, const void* src) {
    asm volatile("cp.async.cg.shared.global [%0], [%1], 16;" :: "r"(dst), "l"(src));
}
__device__ __forceinline__ void cp16ca(uint32_t dst, const void* src) {
    asm volatile("cp.async.ca.shared.global [%0], [%1], 16;" :: "r"(dst), "l"(src));
}
__device__ __forceinline__ void cp_commit() { asm volatile("cp.async.commit_group;"); }
template <int N> __device__ __forceinline__ void cp_wait() {
    asm volatile("cp.async.wait_group %0;" :: "n"(N));
}
__device__ __forceinline__ void mma_tf32(float d[4],
                                         uint32_t a0, uint32_t a1, uint32_t a2, uint32_t a3,
                                         uint32_t b0, uint32_t b1) {
    asm volatile("mma.sync.aligned.m16n8k8.row.col.f32.tf32.tf32.f32 "
                 "{%0,%1,%2,%3}, {%4,%5,%6,%7}, {%8,%9}, {%0,%1,%2,%3};"
                 : "+f"(d[0]), "+f"(d[1]), "+f"(d[2]), "+f"(d[3])
                 : "r"(a0), "r"(a1), "r"(a2), "r"(a3), "r"(b0), "r"(b1));
}
__device__ __forceinline__ uint32_t f2u(float f) { return __float_as_uint(f); }

__global__ void prep_kernel(const float* __restrict__ norm_w,
                            const float* __restrict__ W_pre,
                            const float* __restrict__ W_post,
                            const float* __restrict__ W_res,
                            const float* __restrict__ a_pre,
                            const float* __restrict__ a_post,
                            const float* __restrict__ a_res) {
    int idx = blockIdx.x * blockDim.x + threadIdx.x;
    if (idx >= NJ * KDIM) return;
    int j = idx / KDIM;
    int k = idx - j * KDIM;
    float w, a;
    if (j < 4)      { w = W_pre [j * KDIM + k];       a = a_pre[0];  }
    else if (j < 8) { w = W_post[(j - 4) * KDIM + k]; a = a_post[0]; }
    else            { w = W_res [(j - 8) * KDIM + k]; a = a_res[0];  }
    g_Wt[j * KDIM + k] = w * a * norm_w[k];
}

__global__ __launch_bounds__(BLOCK, 1)
void mhc_mma_kernel(const float* __restrict__ x,
                    const float* __restrict__ b_pre,
                    const float* __restrict__ b_post,
                    const float* __restrict__ b_res,
                    float* __restrict__ out, int Btot) {
    extern __shared__ float dsm[];
    __shared__ float ssqp[MM];

    const int tid  = threadIdx.x;
    const int lane = tid & 31;
    const int warp = tid >> 5;
    const int g    = lane >> 2;       // groupID
    const int c4   = lane & 3;        // threadID_in_group
    const int rowbase = blockIdx.x * MM;

    // ---- async chunk loader ----
    const float* xrow = x + (size_t)rowbase * KDIM;
    const uint32_t sbase = smem_u32(dsm);
    auto issue_chunk = [&](int c) {
        const int s = c % NSTG;
        const uint32_t ab = sbase + s * (STAGEF * 4);
        const float* xb = xrow + c * KC;
#pragma unroll
        for (int i = 0; i < 8; i++) {            // 2048 cp16 for x, 8/thread
            int idx = i * BLOCK + tid;
            int r = idx >> 3, u = idx & 7;
            cp16cg(ab + r * (XSTR * 4) + u * 16,
                   xb + (size_t)r * KDIM + u * 4);
        }
        if (tid < NJ * 8) {                      // 192 cp16 for W
            int j = tid >> 3, u = tid & 7;
            cp16ca(ab + WOFF * 4 + j * (XSTR * 4) + u * 16,
                   g_Wt + (size_t)j * KDIM + c * KC + u * 4);
        }
        cp_commit();
    };

    issue_chunk(0); issue_chunk(1); issue_chunk(2); issue_chunk(3);

    // D accumulators: [mtile][ntile][4]
    float d[2][3][4];
#pragma unroll
    for (int mt = 0; mt < 2; mt++)
#pragma unroll
        for (int n = 0; n < 3; n++)
#pragma unroll
            for (int q = 0; q < 4; q++) d[mt][n][q] = 0.0f;

    // per-thread fragment offsets (floats, within stage)
    const int m0 = warp * 32;
    const int aof0 = (m0 + g) * XSTR + c4;            // tile0 row g
    const int aof1 = aof0 + 8 * XSTR;                 // tile0 row g+8
    const int aof2 = aof0 + 16 * XSTR;                // tile1 row g
    const int aof3 = aof0 + 24 * XSTR;                // tile1 row g+8
    const int bof0 = WOFF + (0 + g) * XSTR + c4;
    const int bof1 = WOFF + (8 + g) * XSTR + c4;
    const int bof2 = WOFF + (16 + g) * XSTR + c4;

    float ssq = 0.0f;

    for (int c = 0; c < NC; ++c) {
        const int rem = NC - 1 - c;
        if (rem >= 3) cp_wait<3>();
        else if (rem == 2) cp_wait<2>();
        else if (rem == 1) cp_wait<1>();
        else cp_wait<0>();
        __syncthreads();                          // chunk c resident; chunk c-1 consumed by all
        if (c + 4 < NC) issue_chunk(c + 4);       // overwrites buffer of c-1 (safe post-barrier)

        const float* fs = dsm + (c % NSTG) * STAGEF;

        // ssq: thread owns row tid (exact fp32)
        {
            const float4* xr = (const float4*)(fs + tid * XSTR);
#pragma unroll
            for (int i = 0; i < 8; i++) {
                float4 v = xr[i];
                ssq += v.x * v.x + v.y * v.y + v.z * v.z + v.w * v.w;
            }
        }

        // MMA: 4 k8-steps
#pragma unroll
        for (int ks = 0; ks < 4; ks++) {
            const int k0 = ks * 8;
            uint32_t A0[4], A1[4];
            A0[0] = f2u(fs[aof0 + k0]);     A0[1] = f2u(fs[aof1 + k0]);
            A0[2] = f2u(fs[aof0 + k0 + 4]); A0[3] = f2u(fs[aof1 + k0 + 4]);
            A1[0] = f2u(fs[aof2 + k0]);     A1[1] = f2u(fs[aof3 + k0]);
            A1[2] = f2u(fs[aof2 + k0 + 4]); A1[3] = f2u(fs[aof3 + k0 + 4]);
            uint32_t b0, b1;
            b0 = f2u(fs[bof0 + k0]); b1 = f2u(fs[bof0 + k0 + 4]);
            mma_tf32(d[0][0], A0[0], A0[1], A0[2], A0[3], b0, b1);
            mma_tf32(d[1][0], A1[0], A1[1], A1[2], A1[3], b0, b1);
            b0 = f2u(fs[bof1 + k0]); b1 = f2u(fs[bof1 + k0 + 4]);
            mma_tf32(d[0][1], A0[0], A0[1], A0[2], A0[3], b0, b1);
            mma_tf32(d[1][1], A1[0], A1[1], A1[2], A1[3], b0, b1);
            b0 = f2u(fs[bof2 + k0]); b1 = f2u(fs[bof2 + k0 + 4]);
            mma_tf32(d[0][2], A0[0], A0[1], A0[2], A0[3], b0, b1);
            mma_tf32(d[1][2], A1[0], A1[1], A1[2], A1[3], b0, b1);
        }
    }

    ssqp[tid] = ssq;
    __syncthreads();                              // all MMA reads done -> reuse dsm for sD

    // transpose D through smem: sD[row][j], stride 28
    float* sD = dsm;
#pragma unroll
    for (int mt = 0; mt < 2; mt++) {
        const int r0 = m0 + mt * 16 + g;
#pragma unroll
        for (int n = 0; n < 3; n++) {
            *(float2*)&sD[r0 * SDSTR + 8 * n + 2 * c4] =
                make_float2(d[mt][n][0], d[mt][n][1]);
            *(float2*)&sD[(r0 + 8) * SDSTR + 8 * n + 2 * c4] =
                make_float2(d[mt][n][2], d[mt][n][3]);
        }
    }
    __syncthreads();

    // epilogue: one row per thread
    {
        const int row = rowbase + tid;
        const float* a = &sD[tid * SDSTR];
        const float rinv = rsqrtf(ssqp[tid] * (1.0f / (float)KDIM) + RMS_EPS);

        float4 o;
        {
            float p0 = rinv * a[0] + b_pre[0];
            float p1 = rinv * a[1] + b_pre[1];
            float p2 = rinv * a[2] + b_pre[2];
            float p3 = rinv * a[3] + b_pre[3];
            o.x = __fdividef(1.0f, 1.0f + __expf(-p0));
            o.y = __fdividef(1.0f, 1.0f + __expf(-p1));
            o.z = __fdividef(1.0f, 1.0f + __expf(-p2));
            o.w = __fdividef(1.0f, 1.0f + __expf(-p3));
            *(float4*)(out + (size_t)row * 4) = o;
        }
        {
            float p0 = rinv * a[4] + b_post[0];
            float p1 = rinv * a[5] + b_post[1];
            float p2 = rinv * a[6] + b_post[2];
            float p3 = rinv * a[7] + b_post[3];
            o.x = 2.0f * __fdividef(1.0f, 1.0f + __expf(-p0));
            o.y = 2.0f * __fdividef(1.0f, 1.0f + __expf(-p1));
            o.z = 2.0f * __fdividef(1.0f, 1.0f + __expf(-p2));
            o.w = 2.0f * __fdividef(1.0f, 1.0f + __expf(-p3));
            *(float4*)(out + (size_t)Btot * 4 + (size_t)row * 4) = o;
        }

        float M[16];
#pragma unroll
        for (int j = 0; j < 16; j++)
            M[j] = __expf(rinv * a[8 + j] + b_res[j]);
#pragma unroll 1
        for (int it = 0; it < 20; it++) {
#pragma unroll
            for (int r = 0; r < 4; r++) {
                float s = M[4*r] + M[4*r+1] + M[4*r+2] + M[4*r+3] + SK_EPS;
                float inv = __fdividef(1.0f, s);
                M[4*r] *= inv; M[4*r+1] *= inv; M[4*r+2] *= inv; M[4*r+3] *= inv;
            }
#pragma unroll
            for (int cq = 0; cq < 4; cq++) {
                float s = M[cq] + M[cq+4] + M[cq+8] + M[cq+12] + SK_EPS;
                float inv = __fdividef(1.0f, s);
                M[cq] *= inv; M[cq+4] *= inv; M[cq+8] *= inv; M[cq+12] *= inv;
            }
        }
        float* ro = out + (size_t)Btot * 8 + (size_t)row * 16;
#pragma unroll
        for (int q = 0; q < 4; q++) {
            o.x = M[4*q]; o.y = M[4*q+1]; o.z = M[4*q+2]; o.w = M[4*q+3];
            *(float4*)(ro + 4 * q) = o;
        }
    }
}

extern "C" void kernel_launch(void* const* d_in, const int* in_sizes, int n_in,
                              void* d_out, int out_size) {
    const float* x      = (const float*)d_in[0];
    const float* norm_w = (const float*)d_in[1];
    const float* W_pre  = (const float*)d_in[2];
    const float* W_post = (const float*)d_in[3];
    const float* W_res  = (const float*)d_in[4];
    const float* b_pre  = (const float*)d_in[5];
    const float* b_post = (const float*)d_in[6];
    const float* b_res  = (const float*)d_in[7];
    const float* a_pre  = (const float*)d_in[8];
    const float* a_post = (const float*)d_in[9];
    const float* a_res  = (const float*)d_in[10];

    const int Btot = in_sizes[0] / KDIM;

    cudaFuncSetAttribute(mhc_mma_kernel,
                         cudaFuncAttributeMaxDynamicSharedMemorySize,
                         SMEM_BYTES);

    prep_kernel<<<(NJ * KDIM + 255) / 256, 256>>>(norm_w, W_pre, W_post, W_res,
                                                  a_pre, a_post, a_res);
    mhc_mma_kernel<<<Btot / MM, BLOCK, SMEM_BYTES>>>(x, b_pre, b_post, b_res,
                                                     (float*)d_out, Btot);
}